// round 10
// baseline (speedup 1.0000x reference)
#include <cuda_runtime.h>
#include <cuda_fp16.h>
#include <cstdint>

// ============================================================
// LSTM cell, sm_103 legacy-HMMA path (tcgen05 unavailable in this
// PTX target). GEMM M=4096, N=8192, K=4096 fp16->fp32, fused epilogue.
// R9 = R8 + persistent GEMM CTAs: next tile's pipeline fill is
// issued BEFORE the current tile's epilogue, overlapping the two.
// GEMM inner loop is FROZEN (R5 config, verified fastest).
// ============================================================

#define BROWS 4096
#define DIN   2048
#define UNITS 2048
#define KTOT  4096
#define NTOT  8192

#define BM 128
#define BN 128
#define BK 64
#define NITER (KTOT / BK)    // 64
#define STAGES 3
#define NTILES ((BROWS / BM) * (NTOT / BN))   // 2048

// SMEM rows: 64 halfs (128B) + 16B pad = 144B
#define ROWB 144
#define ATILE (BM * ROWB)              // 18432 per stage
#define BTILE (BN * ROWB)              // 18432
#define SM_BOFF (STAGES * ATILE)       // 55296
#define SMEM_TOTAL (STAGES * (ATILE + BTILE))   // 110592 (2 CTAs/SM)

// -------- device scratch --------
__device__ __half g_Z [(size_t)BROWS * KTOT];    // 32 MB
__device__ __half g_Wt[(size_t)NTOT  * KTOT];    // 64 MB, n = u*4+gate

// -------- helpers --------
__device__ __forceinline__ uint32_t smem_u32(const void* p) {
    uint32_t a;
    asm("{ .reg .u64 t; cvta.to.shared.u64 t, %1; cvt.u32.u64 %0, t; }" : "=r"(a) : "l"(p));
    return a;
}
__device__ __forceinline__ void cp16(uint32_t dst, const void* src) {
    asm volatile("cp.async.cg.shared.global [%0], [%1], 16;" :: "r"(dst), "l"(src));
}
#define CP_COMMIT() asm volatile("cp.async.commit_group;" ::: "memory")
#define CP_WAIT(n)  asm volatile("cp.async.wait_group %0;" :: "n"(n) : "memory")

__device__ __forceinline__ float sigf(float x)      { return 1.f / (1.f + __expf(-x)); }
__device__ __forceinline__ float tanhfast(float x)  { return 1.f - 2.f / (__expf(2.f * x) + 1.f); }

// tile index -> (m0, n0), GM=8 supertile order (R5 mapping)
__device__ __forceinline__ void tile_coords(int t, int& m0, int& n0) {
    const int NTN = NTOT / BN;       // 64
    const int GM = 8;
    int g = t / (GM * NTN), r = t % (GM * NTN);
    int mt = g * GM + (r % GM);
    int nt = r / GM;
    m0 = mt * BM;
    n0 = nt * BN;
}

// ============================================================
// K1: pack z = [x | h] -> fp16, 8 elements per thread, vectorized
// ============================================================
__global__ void pack_z_kernel(const float* __restrict__ x, const float* __restrict__ h) {
    int i = blockIdx.x * blockDim.x + threadIdx.x;     // over 4096*4096/8
    int row = i >> 9;
    int col = (i & 511) << 3;
    const float* src = (col < DIN) ? x + (size_t)row * DIN + col
                                   : h + (size_t)row * UNITS + (col - DIN);
    float4 a = reinterpret_cast<const float4*>(src)[0];
    float4 b = reinterpret_cast<const float4*>(src)[1];
    __half2 p0 = __floats2half2_rn(a.x, a.y);
    __half2 p1 = __floats2half2_rn(a.z, a.w);
    __half2 p2 = __floats2half2_rn(b.x, b.y);
    __half2 p3 = __floats2half2_rn(b.z, b.w);
    uint4 o;
    o.x = *reinterpret_cast<uint32_t*>(&p0);
    o.y = *reinterpret_cast<uint32_t*>(&p1);
    o.z = *reinterpret_cast<uint32_t*>(&p2);
    o.w = *reinterpret_cast<uint32_t*>(&p3);
    reinterpret_cast<uint4*>(g_Z)[i] = o;
}

// ============================================================
// K2: Wt[n][k] = W_gate[k][u] fp16, n = u*4 + gate (K contiguous)
// 64x64 tiles, float4 loads, uint4 stores, pad 65 (2-way conflicts).
// grid (64,32,4), block (16,16)
// ============================================================
__global__ void transpose_w_kernel(const float* __restrict__ Wf, const float* __restrict__ Wi,
                                   const float* __restrict__ Wc, const float* __restrict__ Wo) {
    __shared__ float t[64][65];
    int k0 = blockIdx.x * 64;
    int u0 = blockIdx.y * 64;
    int gz = blockIdx.z;
    const float* W = (gz == 0) ? Wf : (gz == 1) ? Wi : (gz == 2) ? Wc : Wo;
    int tx = threadIdx.x, ty = threadIdx.y;
    int tid = ty * 16 + tx;

    #pragma unroll
    for (int r = ty; r < 64; r += 16) {
        float4 v = *reinterpret_cast<const float4*>(&W[(size_t)(k0 + r) * UNITS + u0 + 4 * tx]);
        t[r][4 * tx + 0] = v.x;
        t[r][4 * tx + 1] = v.y;
        t[r][4 * tx + 2] = v.z;
        t[r][4 * tx + 3] = v.w;
    }
    __syncthreads();

    #pragma unroll
    for (int it = 0; it < 2; ++it) {
        int idx = tid + it * 256;
        int uu = idx >> 3;
        int kc = idx & 7;
        int n = (u0 + uu) * 4 + gz;
        __half2 hp[4];
        #pragma unroll
        for (int q = 0; q < 4; ++q)
            hp[q] = __floats2half2_rn(t[kc * 8 + 2 * q][uu], t[kc * 8 + 2 * q + 1][uu]);
        uint4 o;
        o.x = *reinterpret_cast<uint32_t*>(&hp[0]);
        o.y = *reinterpret_cast<uint32_t*>(&hp[1]);
        o.z = *reinterpret_cast<uint32_t*>(&hp[2]);
        o.w = *reinterpret_cast<uint32_t*>(&hp[3]);
        *reinterpret_cast<uint4*>(&g_Wt[(size_t)n * KTOT + k0 + kc * 8]) = o;
    }
}

// ============================================================
// K3: persistent GEMM + fused LSTM epilogue
// ============================================================
__device__ __forceinline__ void load_stage(uint32_t sb, int tid, int m0, int n0,
                                           int s, int buf) {
    const int k0 = s * BK;
    #pragma unroll
    for (int j = 0; j < 4; ++j) {               // A: 1024 chunks of 16B
        int c   = tid + j * 256;
        int row = c >> 3, kc = c & 7;
        uint32_t d = sb + buf * ATILE + row * ROWB + kc * 16;
        cp16(d, &g_Z[(size_t)(m0 + row) * KTOT + k0 + kc * 8]);
    }
    #pragma unroll
    for (int j = 0; j < 4; ++j) {               // B: 1024 chunks of 16B
        int c   = tid + j * 256;
        int row = c >> 3, kc = c & 7;
        uint32_t d = sb + SM_BOFF + buf * BTILE + row * ROWB + kc * 16;
        cp16(d, &g_Wt[(size_t)(n0 + row) * KTOT + k0 + kc * 8]);
    }
}

__device__ __forceinline__ void compute_stage(uint32_t aBase, uint32_t bBase,
                                              int warp_m, int warp_n, int lane,
                                              float acc[4][4][4]) {
    #pragma unroll
    for (int ks = 0; ks < 4; ++ks) {            // four k16 steps per BK=64
        uint32_t a[4][4];
        uint32_t b[4][2];
        #pragma unroll
        for (int mi = 0; mi < 4; ++mi) {
            uint32_t addr = aBase + (uint32_t)(warp_m * 64 + mi * 16 + (lane & 15)) * ROWB
                          + ks * 32 + ((lane >> 4) << 4);
            asm volatile("ldmatrix.sync.aligned.m8n8.x4.shared.b16 {%0,%1,%2,%3}, [%4];"
                : "=r"(a[mi][0]), "=r"(a[mi][1]), "=r"(a[mi][2]), "=r"(a[mi][3])
                : "r"(addr));
        }
        int l16 = lane & 15;
        #pragma unroll
        for (int ni = 0; ni < 4; ++ni) {
            uint32_t addr = bBase + (uint32_t)(warp_n * 32 + ni * 8 + (l16 & 7)) * ROWB
                          + ks * 32 + ((l16 >> 3) << 4);
            asm volatile("ldmatrix.sync.aligned.m8n8.x2.shared.b16 {%0,%1}, [%2];"
                : "=r"(b[ni][0]), "=r"(b[ni][1])
                : "r"(addr));
        }
        #pragma unroll
        for (int mi = 0; mi < 4; ++mi)
            #pragma unroll
            for (int ni = 0; ni < 4; ++ni)
                asm volatile("mma.sync.aligned.m16n8k16.row.col.f32.f16.f16.f32 "
                    "{%0,%1,%2,%3}, {%4,%5,%6,%7}, {%8,%9}, {%0,%1,%2,%3};"
                    : "+f"(acc[mi][ni][0]), "+f"(acc[mi][ni][1]),
                      "+f"(acc[mi][ni][2]), "+f"(acc[mi][ni][3])
                    : "r"(a[mi][0]), "r"(a[mi][1]), "r"(a[mi][2]), "r"(a[mi][3]),
                      "r"(b[ni][0]), "r"(b[ni][1]));
    }
}

__global__ void __launch_bounds__(256, 2) gemm_lstm_kernel(
    const float* __restrict__ cin,
    const float* __restrict__ bfv, const float* __restrict__ biv,
    const float* __restrict__ bcv, const float* __restrict__ bov,
    float* __restrict__ out) {
    extern __shared__ char smem[];
    const uint32_t sb = smem_u32(smem);
    const int tid = threadIdx.x, wid = tid >> 5, lane = tid & 31;
    const int warp_m = wid & 1;      // 2 warp rows of 64
    const int warp_n = wid >> 1;     // 4 warp cols of 32

    bool prefetched = false;

    for (int t = blockIdx.x; t < NTILES; t += gridDim.x) {
        int m0, n0;
        tile_coords(t, m0, n0);

        float acc[4][4][4];
        #pragma unroll
        for (int mi = 0; mi < 4; ++mi)
            #pragma unroll
            for (int ni = 0; ni < 4; ++ni)
                #pragma unroll
                for (int q = 0; q < 4; ++q) acc[mi][ni][q] = 0.f;

        if (!prefetched) {      // first tile only: fill stages 0,1
            load_stage(sb, tid, m0, n0, 0, 0); CP_COMMIT();
            load_stage(sb, tid, m0, n0, 1, 1); CP_COMMIT();
        }

        for (int i = 0; i < NITER; ++i) {
            if (i + 2 < NITER) {
                CP_WAIT(1);
                __syncthreads();
                load_stage(sb, tid, m0, n0, i + 2, (i + 2) % STAGES);
                CP_COMMIT();
            } else if (i + 2 == NITER) {
                CP_WAIT(1);
                __syncthreads();
            } else {
                CP_WAIT(0);
                __syncthreads();
            }
            int buf = i % STAGES;
            compute_stage(sb + buf * ATILE, sb + SM_BOFF + buf * BTILE,
                          warp_m, warp_n, lane, acc);
        }

        // all warps finished reading smem; prefetch next tile's stages 0,1
        // into buffers 0,1 BEFORE the epilogue so loads fly under it.
        __syncthreads();
        int tn = t + gridDim.x;
        if (tn < NTILES) {
            int m1, n1;
            tile_coords(tn, m1, n1);
            load_stage(sb, tid, m1, n1, 0, 0); CP_COMMIT();
            load_stage(sb, tid, m1, n1, 1, 1); CP_COMMIT();
            prefetched = true;
        }

        // ---------------- fused LSTM epilogue ----------------
        // Cols gate-interleaved: n = u*4 + gate. Thread col pair is (f,i)
        // [even lane] or (c,o) [odd lane] of unit u; one bfly-1 shuffle
        // completes the quad: even lane -> row r, odd lane -> row r+8.
        #pragma unroll
        for (int mi = 0; mi < 4; ++mi) {
            #pragma unroll
            for (int ni = 0; ni < 4; ++ni) {
                int rbase = m0 + warp_m * 64 + mi * 16 + (lane >> 2);
                int u = ((n0 + warp_n * 32 + ni * 8) >> 2) + ((lane & 3) >> 1);
                float d0 = acc[mi][ni][0], d1 = acc[mi][ni][1];
                float d2 = acc[mi][ni][2], d3 = acc[mi][ni][3];
                float s0 = (lane & 1) ? d0 : d2;
                float s1 = (lane & 1) ? d1 : d3;
                float t0 = __shfl_xor_sync(0xffffffffu, s0, 1);
                float t1 = __shfl_xor_sync(0xffffffffu, s1, 1);
                float fg, ig, cg, og; int row;
                if (!(lane & 1)) { fg = d0; ig = d1; cg = t0; og = t1; row = rbase; }
                else             { fg = t0; ig = t1; cg = d2; og = d3; row = rbase + 8; }
                fg += __ldg(&bfv[u]); ig += __ldg(&biv[u]);
                cg += __ldg(&bcv[u]); og += __ldg(&bov[u]);
                float ft = sigf(fg), it = sigf(ig);
                float gt = tanhfast(cg), ot = sigf(og);
                size_t idx = (size_t)row * UNITS + u;
                float nc = ft * __ldg(&cin[idx]) + it * gt;
                float nh = ot * tanhfast(nc);
                out[idx] = nh;                                   // new_h
                out[(size_t)BROWS * UNITS + idx] = nc;           // new_c
            }
        }
    }
}

// ============================================================
// kernel_launch — K1 || K2 fork/join, then persistent K3.
// ============================================================
extern "C" void kernel_launch(void* const* d_in, const int* in_sizes, int n_in,
                              void* d_out, int out_size) {
    const float* x  = (const float*)d_in[0];
    const float* h  = (const float*)d_in[1];
    const float* c  = (const float*)d_in[2];
    const float* Wf = (const float*)d_in[3];
    const float* bf = (const float*)d_in[4];
    const float* Wi = (const float*)d_in[5];
    const float* bi = (const float*)d_in[6];
    const float* Wc = (const float*)d_in[7];
    const float* bc = (const float*)d_in[8];
    const float* Wo = (const float*)d_in[9];
    const float* bo = (const float*)d_in[10];
    float* out = (float*)d_out;

    static cudaStream_t s2 = nullptr;
    static cudaEvent_t evFork = nullptr, evJoin = nullptr;
    static int gemmGrid = 0;
    if (!gemmGrid) {
        cudaStreamCreateWithFlags(&s2, cudaStreamNonBlocking);
        cudaEventCreateWithFlags(&evFork, cudaEventDisableTiming);
        cudaEventCreateWithFlags(&evJoin, cudaEventDisableTiming);
        cudaFuncSetAttribute(gemm_lstm_kernel,
                             cudaFuncAttributeMaxDynamicSharedMemorySize, SMEM_TOTAL);
        int sm = 0, dev = 0;
        cudaGetDevice(&dev);
        cudaDeviceGetAttribute(&sm, cudaDevAttrMultiProcessorCount, dev);
        gemmGrid = 2 * sm;            // 2 CTAs resident per SM
        if (gemmGrid <= 0 || gemmGrid > NTILES) gemmGrid = 296;
    }

    // fork: pack_z on main stream, transpose_w on s2 (independent)
    cudaEventRecord(evFork, 0);
    cudaStreamWaitEvent(s2, evFork, 0);

    pack_z_kernel<<<(BROWS * KTOT / 8) / 256, 256>>>(x, h);

    dim3 tg(KTOT / 64, UNITS / 64, 4);
    transpose_w_kernel<<<tg, dim3(16, 16), 0, s2>>>(Wf, Wi, Wc, Wo);

    // join back to main stream
    cudaEventRecord(evJoin, s2);
    cudaStreamWaitEvent(0, evJoin, 0);

    gemm_lstm_kernel<<<gemmGrid, 256, SMEM_TOTAL>>>(c, bf, bi, bc, bo, out);
}

// round 11
// speedup vs baseline: 1.0819x; 1.0819x over previous
#include <cuda_runtime.h>
#include <cuda_fp16.h>
#include <cstdint>

// ============================================================
// LSTM cell, sm_103 legacy-HMMA path (tcgen05 unavailable in this
// PTX target). GEMM M=4096, N=8192, K=4096 fp16->fp32, fused epilogue.
// R10 = R8 GEMM core byte-identical (verified 797us, FROZEN),
// pre-pass pipelined: transpose split in 2 halves; GEMM split in 2
// independent chunk launches so half the transpose hides under chunk1.
// ============================================================

#define BROWS 4096
#define DIN   2048
#define UNITS 2048
#define KTOT  4096
#define NTOT  8192

#define BM 128
#define BN 128
#define BK 64
#define NITER (KTOT / BK)    // 64
#define STAGES 3

// SMEM rows: 64 halfs (128B) + 16B pad = 144B
#define ROWB 144
#define ATILE (BM * ROWB)              // 18432 per stage
#define BTILE (BN * ROWB)              // 18432
#define SM_BOFF (STAGES * ATILE)       // 55296
#define SMEM_TOTAL (STAGES * (ATILE + BTILE))   // 110592 (2 CTAs/SM)

// -------- device scratch --------
__device__ __half g_Z [(size_t)BROWS * KTOT];    // 32 MB
__device__ __half g_Wt[(size_t)NTOT  * KTOT];    // 64 MB, n = u*4+gate

// -------- helpers --------
__device__ __forceinline__ uint32_t smem_u32(const void* p) {
    uint32_t a;
    asm("{ .reg .u64 t; cvta.to.shared.u64 t, %1; cvt.u32.u64 %0, t; }" : "=r"(a) : "l"(p));
    return a;
}
__device__ __forceinline__ void cp16(uint32_t dst, const void* src) {
    asm volatile("cp.async.cg.shared.global [%0], [%1], 16;" :: "r"(dst), "l"(src));
}
#define CP_COMMIT() asm volatile("cp.async.commit_group;" ::: "memory")
#define CP_WAIT(n)  asm volatile("cp.async.wait_group %0;" :: "n"(n) : "memory")

__device__ __forceinline__ float sigf(float x)      { return 1.f / (1.f + __expf(-x)); }
__device__ __forceinline__ float tanhfast(float x)  { return 1.f - 2.f / (__expf(2.f * x) + 1.f); }

// ============================================================
// K1: pack z = [x | h] -> fp16, 8 elements per thread, vectorized
// ============================================================
__global__ void pack_z_kernel(const float* __restrict__ x, const float* __restrict__ h) {
    int i = blockIdx.x * blockDim.x + threadIdx.x;     // over 4096*4096/8
    int row = i >> 9;
    int col = (i & 511) << 3;
    const float* src = (col < DIN) ? x + (size_t)row * DIN + col
                                   : h + (size_t)row * UNITS + (col - DIN);
    float4 a = reinterpret_cast<const float4*>(src)[0];
    float4 b = reinterpret_cast<const float4*>(src)[1];
    __half2 p0 = __floats2half2_rn(a.x, a.y);
    __half2 p1 = __floats2half2_rn(a.z, a.w);
    __half2 p2 = __floats2half2_rn(b.x, b.y);
    __half2 p3 = __floats2half2_rn(b.z, b.w);
    uint4 o;
    o.x = *reinterpret_cast<uint32_t*>(&p0);
    o.y = *reinterpret_cast<uint32_t*>(&p1);
    o.z = *reinterpret_cast<uint32_t*>(&p2);
    o.w = *reinterpret_cast<uint32_t*>(&p3);
    reinterpret_cast<uint4*>(g_Z)[i] = o;
}

// ============================================================
// K2: Wt[n][k] = W_gate[k][u] fp16, n = u*4 + gate (K contiguous)
// 64x64 tiles, float4 loads, uint4 stores, pad 65 (2-way conflicts).
// u_base selects which half of the units this launch covers.
// grid (64,16,4), block (16,16)
// ============================================================
__global__ void transpose_w_kernel(const float* __restrict__ Wf, const float* __restrict__ Wi,
                                   const float* __restrict__ Wc, const float* __restrict__ Wo,
                                   int u_base) {
    __shared__ float t[64][65];
    int k0 = blockIdx.x * 64;
    int u0 = u_base + blockIdx.y * 64;
    int gz = blockIdx.z;
    const float* W = (gz == 0) ? Wf : (gz == 1) ? Wi : (gz == 2) ? Wc : Wo;
    int tx = threadIdx.x, ty = threadIdx.y;
    int tid = ty * 16 + tx;

    #pragma unroll
    for (int r = ty; r < 64; r += 16) {
        float4 v = *reinterpret_cast<const float4*>(&W[(size_t)(k0 + r) * UNITS + u0 + 4 * tx]);
        t[r][4 * tx + 0] = v.x;
        t[r][4 * tx + 1] = v.y;
        t[r][4 * tx + 2] = v.z;
        t[r][4 * tx + 3] = v.w;
    }
    __syncthreads();

    #pragma unroll
    for (int it = 0; it < 2; ++it) {
        int idx = tid + it * 256;
        int uu = idx >> 3;
        int kc = idx & 7;
        int n = (u0 + uu) * 4 + gz;
        __half2 hp[4];
        #pragma unroll
        for (int q = 0; q < 4; ++q)
            hp[q] = __floats2half2_rn(t[kc * 8 + 2 * q][uu], t[kc * 8 + 2 * q + 1][uu]);
        uint4 o;
        o.x = *reinterpret_cast<uint32_t*>(&hp[0]);
        o.y = *reinterpret_cast<uint32_t*>(&hp[1]);
        o.z = *reinterpret_cast<uint32_t*>(&hp[2]);
        o.w = *reinterpret_cast<uint32_t*>(&hp[3]);
        *reinterpret_cast<uint4*>(&g_Wt[(size_t)n * KTOT + k0 + kc * 8]) = o;
    }
}

// ============================================================
// K3: GEMM (BK=64, 3 stages) + fused LSTM epilogue  [R8 core, FROZEN]
// Launched twice as independent chunks (nt_base = 0 and 32).
// ============================================================
__device__ __forceinline__ void load_stage(uint32_t sb, int tid, int m0, int n0,
                                           int s, int buf) {
    const int k0 = s * BK;
    #pragma unroll
    for (int j = 0; j < 4; ++j) {               // A: 1024 chunks of 16B
        int c   = tid + j * 256;
        int row = c >> 3, kc = c & 7;
        uint32_t d = sb + buf * ATILE + row * ROWB + kc * 16;
        cp16(d, &g_Z[(size_t)(m0 + row) * KTOT + k0 + kc * 8]);
    }
    #pragma unroll
    for (int j = 0; j < 4; ++j) {               // B: 1024 chunks of 16B
        int c   = tid + j * 256;
        int row = c >> 3, kc = c & 7;
        uint32_t d = sb + SM_BOFF + buf * BTILE + row * ROWB + kc * 16;
        cp16(d, &g_Wt[(size_t)(n0 + row) * KTOT + k0 + kc * 8]);
    }
}

__device__ __forceinline__ void compute_stage(uint32_t aBase, uint32_t bBase,
                                              int warp_m, int warp_n, int lane,
                                              float acc[4][4][4]) {
    #pragma unroll
    for (int ks = 0; ks < 4; ++ks) {            // four k16 steps per BK=64
        uint32_t a[4][4];
        uint32_t b[4][2];
        #pragma unroll
        for (int mi = 0; mi < 4; ++mi) {
            uint32_t addr = aBase + (uint32_t)(warp_m * 64 + mi * 16 + (lane & 15)) * ROWB
                          + ks * 32 + ((lane >> 4) << 4);
            asm volatile("ldmatrix.sync.aligned.m8n8.x4.shared.b16 {%0,%1,%2,%3}, [%4];"
                : "=r"(a[mi][0]), "=r"(a[mi][1]), "=r"(a[mi][2]), "=r"(a[mi][3])
                : "r"(addr));
        }
        int l16 = lane & 15;
        #pragma unroll
        for (int ni = 0; ni < 4; ++ni) {
            uint32_t addr = bBase + (uint32_t)(warp_n * 32 + ni * 8 + (l16 & 7)) * ROWB
                          + ks * 32 + ((l16 >> 3) << 4);
            asm volatile("ldmatrix.sync.aligned.m8n8.x2.shared.b16 {%0,%1}, [%2];"
                : "=r"(b[ni][0]), "=r"(b[ni][1])
                : "r"(addr));
        }
        #pragma unroll
        for (int mi = 0; mi < 4; ++mi)
            #pragma unroll
            for (int ni = 0; ni < 4; ++ni)
                asm volatile("mma.sync.aligned.m16n8k16.row.col.f32.f16.f16.f32 "
                    "{%0,%1,%2,%3}, {%4,%5,%6,%7}, {%8,%9}, {%0,%1,%2,%3};"
                    : "+f"(acc[mi][ni][0]), "+f"(acc[mi][ni][1]),
                      "+f"(acc[mi][ni][2]), "+f"(acc[mi][ni][3])
                    : "r"(a[mi][0]), "r"(a[mi][1]), "r"(a[mi][2]), "r"(a[mi][3]),
                      "r"(b[ni][0]), "r"(b[ni][1]));
    }
}

__global__ void __launch_bounds__(256, 2) gemm_lstm_kernel(
    const float* __restrict__ cin,
    const float* __restrict__ bfv, const float* __restrict__ biv,
    const float* __restrict__ bcv, const float* __restrict__ bov,
    float* __restrict__ out, int nt_base) {
    extern __shared__ char smem[];
    const uint32_t sb = smem_u32(smem);
    const int tid = threadIdx.x, wid = tid >> 5, lane = tid & 31;
    const int warp_m = wid & 1;      // 2 warp rows of 64
    const int warp_n = wid >> 1;     // 4 warp cols of 32

    // supertile mapping within this 32-ntile chunk: groups of 8 M-tiles
    const int NTN_C = 32;
    const int GM = 8;
    int bid = blockIdx.x;
    int g = bid / (GM * NTN_C), r = bid % (GM * NTN_C);
    int mt = g * GM + (r % GM);
    int nt = nt_base + r / GM;
    int m0 = mt * BM, n0 = nt * BN;

    float acc[4][4][4];
    #pragma unroll
    for (int mi = 0; mi < 4; ++mi)
        #pragma unroll
        for (int ni = 0; ni < 4; ++ni)
            #pragma unroll
            for (int q = 0; q < 4; ++q) acc[mi][ni][q] = 0.f;

    load_stage(sb, tid, m0, n0, 0, 0); CP_COMMIT();
    load_stage(sb, tid, m0, n0, 1, 1); CP_COMMIT();

    for (int i = 0; i < NITER; ++i) {
        if (i + 2 < NITER) {
            CP_WAIT(1);
            __syncthreads();
            load_stage(sb, tid, m0, n0, i + 2, (i + 2) % STAGES);
            CP_COMMIT();
        } else if (i + 2 == NITER) {
            CP_WAIT(1);
            __syncthreads();
        } else {
            CP_WAIT(0);
            __syncthreads();
        }
        int buf = i % STAGES;
        compute_stage(sb + buf * ATILE, sb + SM_BOFF + buf * BTILE,
                      warp_m, warp_n, lane, acc);
    }

    // ---------------- fused LSTM epilogue ----------------
    // Cols gate-interleaved: n = u*4 + gate. Thread col pair is (f,i)
    // [even lane] or (c,o) [odd lane] of unit u; one bfly-1 shuffle
    // completes the quad: even lane -> row r, odd lane -> row r+8.
    #pragma unroll
    for (int mi = 0; mi < 4; ++mi) {
        #pragma unroll
        for (int ni = 0; ni < 4; ++ni) {
            int rbase = m0 + warp_m * 64 + mi * 16 + (lane >> 2);
            int u = ((n0 + warp_n * 32 + ni * 8) >> 2) + ((lane & 3) >> 1);
            float d0 = acc[mi][ni][0], d1 = acc[mi][ni][1];
            float d2 = acc[mi][ni][2], d3 = acc[mi][ni][3];
            float s0 = (lane & 1) ? d0 : d2;
            float s1 = (lane & 1) ? d1 : d3;
            float t0 = __shfl_xor_sync(0xffffffffu, s0, 1);
            float t1 = __shfl_xor_sync(0xffffffffu, s1, 1);
            float fg, ig, cg, og; int row;
            if (!(lane & 1)) { fg = d0; ig = d1; cg = t0; og = t1; row = rbase; }
            else             { fg = t0; ig = t1; cg = d2; og = d3; row = rbase + 8; }
            fg += __ldg(&bfv[u]); ig += __ldg(&biv[u]);
            cg += __ldg(&bcv[u]); og += __ldg(&bov[u]);
            float ft = sigf(fg), it = sigf(ig);
            float gt = tanhfast(cg), ot = sigf(og);
            size_t idx = (size_t)row * UNITS + u;
            float nc = ft * __ldg(&cin[idx]) + it * gt;
            float nh = ot * tanhfast(nc);
            out[idx] = nh;                                   // new_h
            out[(size_t)BROWS * UNITS + idx] = nc;           // new_c
        }
    }
}

// ============================================================
// kernel_launch — pipelined pre-pass + 2 independent GEMM chunks.
//   main: pack_z, (wait T1) gemm chunk1 (nt 0..31)
//   s2:   transpose H1 (u<1024) [evT1], transpose H2 [evT2]
//   s3:   (wait evPack, evT2) gemm chunk2 (nt 32..63)
// ============================================================
extern "C" void kernel_launch(void* const* d_in, const int* in_sizes, int n_in,
                              void* d_out, int out_size) {
    const float* x  = (const float*)d_in[0];
    const float* h  = (const float*)d_in[1];
    const float* c  = (const float*)d_in[2];
    const float* Wf = (const float*)d_in[3];
    const float* bf = (const float*)d_in[4];
    const float* Wi = (const float*)d_in[5];
    const float* bi = (const float*)d_in[6];
    const float* Wc = (const float*)d_in[7];
    const float* bc = (const float*)d_in[8];
    const float* Wo = (const float*)d_in[9];
    const float* bo = (const float*)d_in[10];
    float* out = (float*)d_out;

    static cudaStream_t s2 = nullptr, s3 = nullptr;
    static cudaEvent_t evFork = nullptr, evPack = nullptr, evT1 = nullptr, evT2 = nullptr;
    static bool inited = false;
    if (!inited) {
        cudaStreamCreateWithFlags(&s2, cudaStreamNonBlocking);
        cudaStreamCreateWithFlags(&s3, cudaStreamNonBlocking);
        cudaEventCreateWithFlags(&evFork, cudaEventDisableTiming);
        cudaEventCreateWithFlags(&evPack, cudaEventDisableTiming);
        cudaEventCreateWithFlags(&evT1, cudaEventDisableTiming);
        cudaEventCreateWithFlags(&evT2, cudaEventDisableTiming);
        cudaFuncSetAttribute(gemm_lstm_kernel,
                             cudaFuncAttributeMaxDynamicSharedMemorySize, SMEM_TOTAL);
        inited = true;
    }

    // fork to s2
    cudaEventRecord(evFork, 0);
    cudaStreamWaitEvent(s2, evFork, 0);

    // main: pack z
    pack_z_kernel<<<(BROWS * KTOT / 8) / 256, 256>>>(x, h);
    cudaEventRecord(evPack, 0);

    // s2: transpose halves
    dim3 tgh(KTOT / 64, 16, 4);
    transpose_w_kernel<<<tgh, dim3(16, 16), 0, s2>>>(Wf, Wi, Wc, Wo, 0);
    cudaEventRecord(evT1, s2);
    transpose_w_kernel<<<tgh, dim3(16, 16), 0, s2>>>(Wf, Wi, Wc, Wo, 1024);
    cudaEventRecord(evT2, s2);

    // chunk1 on main: needs pack (program order) + H1
    cudaStreamWaitEvent(0, evT1, 0);
    gemm_lstm_kernel<<<1024, 256, SMEM_TOTAL>>>(c, bf, bi, bc, bo, out, 0);

    // chunk2 on s3: needs pack + H2; runs as chunk1 drains
    cudaStreamWaitEvent(s3, evPack, 0);
    cudaStreamWaitEvent(s3, evT2, 0);
    gemm_lstm_kernel<<<1024, 256, SMEM_TOTAL, s3>>>(c, bf, bi, bc, bo, out, 32);

    // join chunk2 back to main stream so the harness sees completion
    cudaEventRecord(evT2, s3);
    cudaStreamWaitEvent(0, evT2, 0);
}

// round 12
// speedup vs baseline: 1.1192x; 1.0345x over previous
#include <cuda_runtime.h>
#include <cuda_fp16.h>
#include <cstdint>

// ============================================================
// LSTM cell, sm_103 legacy-HMMA path (tcgen05 unavailable in this
// PTX target). GEMM M=4096, N=8192, K=4096 fp16->fp32, fused epilogue.
// R11 = R8 launch structure (verified 797us) with ONE change:
// mma.sync asm is non-volatile so ptxas can interleave next-ks LDSM
// under the current MMA burst (ncu: tensor=57%, issue=22% -> latency).
// ============================================================

#define BROWS 4096
#define DIN   2048
#define UNITS 2048
#define KTOT  4096
#define NTOT  8192

#define BM 128
#define BN 128
#define BK 64
#define NITER (KTOT / BK)    // 64
#define STAGES 3

// SMEM rows: 64 halfs (128B) + 16B pad = 144B
#define ROWB 144
#define ATILE (BM * ROWB)              // 18432 per stage
#define BTILE (BN * ROWB)              // 18432
#define SM_BOFF (STAGES * ATILE)       // 55296
#define SMEM_TOTAL (STAGES * (ATILE + BTILE))   // 110592 (2 CTAs/SM)

// -------- device scratch --------
__device__ __half g_Z [(size_t)BROWS * KTOT];    // 32 MB
__device__ __half g_Wt[(size_t)NTOT  * KTOT];    // 64 MB, n = u*4+gate

// -------- helpers --------
__device__ __forceinline__ uint32_t smem_u32(const void* p) {
    uint32_t a;
    asm("{ .reg .u64 t; cvta.to.shared.u64 t, %1; cvt.u32.u64 %0, t; }" : "=r"(a) : "l"(p));
    return a;
}
__device__ __forceinline__ void cp16(uint32_t dst, const void* src) {
    asm volatile("cp.async.cg.shared.global [%0], [%1], 16;" :: "r"(dst), "l"(src));
}
#define CP_COMMIT() asm volatile("cp.async.commit_group;" ::: "memory")
#define CP_WAIT(n)  asm volatile("cp.async.wait_group %0;" :: "n"(n) : "memory")

__device__ __forceinline__ float sigf(float x)      { return 1.f / (1.f + __expf(-x)); }
__device__ __forceinline__ float tanhfast(float x)  { return 1.f - 2.f / (__expf(2.f * x) + 1.f); }

// ============================================================
// K1: pack z = [x | h] -> fp16, 8 elements per thread, vectorized
// ============================================================
__global__ void pack_z_kernel(const float* __restrict__ x, const float* __restrict__ h) {
    int i = blockIdx.x * blockDim.x + threadIdx.x;     // over 4096*4096/8
    int row = i >> 9;
    int col = (i & 511) << 3;
    const float* src = (col < DIN) ? x + (size_t)row * DIN + col
                                   : h + (size_t)row * UNITS + (col - DIN);
    float4 a = reinterpret_cast<const float4*>(src)[0];
    float4 b = reinterpret_cast<const float4*>(src)[1];
    __half2 p0 = __floats2half2_rn(a.x, a.y);
    __half2 p1 = __floats2half2_rn(a.z, a.w);
    __half2 p2 = __floats2half2_rn(b.x, b.y);
    __half2 p3 = __floats2half2_rn(b.z, b.w);
    uint4 o;
    o.x = *reinterpret_cast<uint32_t*>(&p0);
    o.y = *reinterpret_cast<uint32_t*>(&p1);
    o.z = *reinterpret_cast<uint32_t*>(&p2);
    o.w = *reinterpret_cast<uint32_t*>(&p3);
    reinterpret_cast<uint4*>(g_Z)[i] = o;
}

// ============================================================
// K2: Wt[n][k] = W_gate[k][u] fp16, n = u*4 + gate (K contiguous)
// 64x64 tiles, float4 loads, uint4 stores, pad 65 (2-way conflicts).
// grid (64,32,4), block (16,16)
// ============================================================
__global__ void transpose_w_kernel(const float* __restrict__ Wf, const float* __restrict__ Wi,
                                   const float* __restrict__ Wc, const float* __restrict__ Wo) {
    __shared__ float t[64][65];
    int k0 = blockIdx.x * 64;
    int u0 = blockIdx.y * 64;
    int gz = blockIdx.z;
    const float* W = (gz == 0) ? Wf : (gz == 1) ? Wi : (gz == 2) ? Wc : Wo;
    int tx = threadIdx.x, ty = threadIdx.y;
    int tid = ty * 16 + tx;

    #pragma unroll
    for (int r = ty; r < 64; r += 16) {
        float4 v = *reinterpret_cast<const float4*>(&W[(size_t)(k0 + r) * UNITS + u0 + 4 * tx]);
        t[r][4 * tx + 0] = v.x;
        t[r][4 * tx + 1] = v.y;
        t[r][4 * tx + 2] = v.z;
        t[r][4 * tx + 3] = v.w;
    }
    __syncthreads();

    #pragma unroll
    for (int it = 0; it < 2; ++it) {
        int idx = tid + it * 256;
        int uu = idx >> 3;
        int kc = idx & 7;
        int n = (u0 + uu) * 4 + gz;
        __half2 hp[4];
        #pragma unroll
        for (int q = 0; q < 4; ++q)
            hp[q] = __floats2half2_rn(t[kc * 8 + 2 * q][uu], t[kc * 8 + 2 * q + 1][uu]);
        uint4 o;
        o.x = *reinterpret_cast<uint32_t*>(&hp[0]);
        o.y = *reinterpret_cast<uint32_t*>(&hp[1]);
        o.z = *reinterpret_cast<uint32_t*>(&hp[2]);
        o.w = *reinterpret_cast<uint32_t*>(&hp[3]);
        *reinterpret_cast<uint4*>(&g_Wt[(size_t)n * KTOT + k0 + kc * 8]) = o;
    }
}

// ============================================================
// K3: GEMM (BK=64, 3 stages) + fused LSTM epilogue
// ============================================================
__device__ __forceinline__ void load_stage(uint32_t sb, int tid, int m0, int n0,
                                           int s, int buf) {
    const int k0 = s * BK;
    #pragma unroll
    for (int j = 0; j < 4; ++j) {               // A: 1024 chunks of 16B
        int c   = tid + j * 256;
        int row = c >> 3, kc = c & 7;
        uint32_t d = sb + buf * ATILE + row * ROWB + kc * 16;
        cp16(d, &g_Z[(size_t)(m0 + row) * KTOT + k0 + kc * 8]);
    }
    #pragma unroll
    for (int j = 0; j < 4; ++j) {               // B: 1024 chunks of 16B
        int c   = tid + j * 256;
        int row = c >> 3, kc = c & 7;
        uint32_t d = sb + SM_BOFF + buf * BTILE + row * ROWB + kc * 16;
        cp16(d, &g_Wt[(size_t)(n0 + row) * KTOT + k0 + kc * 8]);
    }
}

__device__ __forceinline__ void compute_stage(uint32_t aBase, uint32_t bBase,
                                              int warp_m, int warp_n, int lane,
                                              float acc[4][4][4]) {
    #pragma unroll
    for (int ks = 0; ks < 4; ++ks) {            // four k16 steps per BK=64
        uint32_t a[4][4];
        uint32_t b[4][2];
        #pragma unroll
        for (int mi = 0; mi < 4; ++mi) {
            uint32_t addr = aBase + (uint32_t)(warp_m * 64 + mi * 16 + (lane & 15)) * ROWB
                          + ks * 32 + ((lane >> 4) << 4);
            asm volatile("ldmatrix.sync.aligned.m8n8.x4.shared.b16 {%0,%1,%2,%3}, [%4];"
                : "=r"(a[mi][0]), "=r"(a[mi][1]), "=r"(a[mi][2]), "=r"(a[mi][3])
                : "r"(addr));
        }
        int l16 = lane & 15;
        #pragma unroll
        for (int ni = 0; ni < 4; ++ni) {
            uint32_t addr = bBase + (uint32_t)(warp_n * 32 + ni * 8 + (l16 & 7)) * ROWB
                          + ks * 32 + ((l16 >> 3) << 4);
            asm volatile("ldmatrix.sync.aligned.m8n8.x2.shared.b16 {%0,%1}, [%2];"
                : "=r"(b[ni][0]), "=r"(b[ni][1])
                : "r"(addr));
        }
        // NON-volatile: no side effects, lets ptxas interleave these MMAs
        // with the next ks-step's ldmatrix issues (dataflow keeps order).
        #pragma unroll
        for (int mi = 0; mi < 4; ++mi)
            #pragma unroll
            for (int ni = 0; ni < 4; ++ni)
                asm("mma.sync.aligned.m16n8k16.row.col.f32.f16.f16.f32 "
                    "{%0,%1,%2,%3}, {%4,%5,%6,%7}, {%8,%9}, {%0,%1,%2,%3};"
                    : "+f"(acc[mi][ni][0]), "+f"(acc[mi][ni][1]),
                      "+f"(acc[mi][ni][2]), "+f"(acc[mi][ni][3])
                    : "r"(a[mi][0]), "r"(a[mi][1]), "r"(a[mi][2]), "r"(a[mi][3]),
                      "r"(b[ni][0]), "r"(b[ni][1]));
    }
}

__global__ void __launch_bounds__(256, 2) gemm_lstm_kernel(
    const float* __restrict__ cin,
    const float* __restrict__ bfv, const float* __restrict__ biv,
    const float* __restrict__ bcv, const float* __restrict__ bov,
    float* __restrict__ out) {
    extern __shared__ char smem[];
    const uint32_t sb = smem_u32(smem);
    const int tid = threadIdx.x, wid = tid >> 5, lane = tid & 31;
    const int warp_m = wid & 1;      // 2 warp rows of 64
    const int warp_n = wid >> 1;     // 4 warp cols of 32

    // L2-friendly supertile mapping: groups of 8 M-tiles per N sweep
    const int NTN = NTOT / BN;       // 64
    const int GM = 8;
    int bid = blockIdx.x;
    int g = bid / (GM * NTN), r = bid % (GM * NTN);
    int mt = g * GM + (r % GM);
    int nt = r / GM;
    int m0 = mt * BM, n0 = nt * BN;

    float acc[4][4][4];
    #pragma unroll
    for (int mi = 0; mi < 4; ++mi)
        #pragma unroll
        for (int ni = 0; ni < 4; ++ni)
            #pragma unroll
            for (int q = 0; q < 4; ++q) acc[mi][ni][q] = 0.f;

    load_stage(sb, tid, m0, n0, 0, 0); CP_COMMIT();
    load_stage(sb, tid, m0, n0, 1, 1); CP_COMMIT();

    for (int i = 0; i < NITER; ++i) {
        if (i + 2 < NITER) {
            CP_WAIT(1);
            __syncthreads();
            load_stage(sb, tid, m0, n0, i + 2, (i + 2) % STAGES);
            CP_COMMIT();
        } else if (i + 2 == NITER) {
            CP_WAIT(1);
            __syncthreads();
        } else {
            CP_WAIT(0);
            __syncthreads();
        }
        int buf = i % STAGES;
        compute_stage(sb + buf * ATILE, sb + SM_BOFF + buf * BTILE,
                      warp_m, warp_n, lane, acc);
    }

    // ---------------- fused LSTM epilogue ----------------
    // Cols gate-interleaved: n = u*4 + gate. Thread col pair is (f,i)
    // [even lane] or (c,o) [odd lane] of unit u; one bfly-1 shuffle
    // completes the quad: even lane -> row r, odd lane -> row r+8.
    #pragma unroll
    for (int mi = 0; mi < 4; ++mi) {
        #pragma unroll
        for (int ni = 0; ni < 4; ++ni) {
            int rbase = m0 + warp_m * 64 + mi * 16 + (lane >> 2);
            int u = ((n0 + warp_n * 32 + ni * 8) >> 2) + ((lane & 3) >> 1);
            float d0 = acc[mi][ni][0], d1 = acc[mi][ni][1];
            float d2 = acc[mi][ni][2], d3 = acc[mi][ni][3];
            float s0 = (lane & 1) ? d0 : d2;
            float s1 = (lane & 1) ? d1 : d3;
            float t0 = __shfl_xor_sync(0xffffffffu, s0, 1);
            float t1 = __shfl_xor_sync(0xffffffffu, s1, 1);
            float fg, ig, cg, og; int row;
            if (!(lane & 1)) { fg = d0; ig = d1; cg = t0; og = t1; row = rbase; }
            else             { fg = t0; ig = t1; cg = d2; og = d3; row = rbase + 8; }
            fg += __ldg(&bfv[u]); ig += __ldg(&biv[u]);
            cg += __ldg(&bcv[u]); og += __ldg(&bov[u]);
            float ft = sigf(fg), it = sigf(ig);
            float gt = tanhfast(cg), ot = sigf(og);
            size_t idx = (size_t)row * UNITS + u;
            float nc = ft * __ldg(&cin[idx]) + it * gt;
            float nh = ot * tanhfast(nc);
            out[idx] = nh;                                   // new_h
            out[(size_t)BROWS * UNITS + idx] = nc;           // new_c
        }
    }
}

// ============================================================
// kernel_launch — K1 || K2 fork/join, then K3 (R8 structure).
// ============================================================
extern "C" void kernel_launch(void* const* d_in, const int* in_sizes, int n_in,
                              void* d_out, int out_size) {
    const float* x  = (const float*)d_in[0];
    const float* h  = (const float*)d_in[1];
    const float* c  = (const float*)d_in[2];
    const float* Wf = (const float*)d_in[3];
    const float* bf = (const float*)d_in[4];
    const float* Wi = (const float*)d_in[5];
    const float* bi = (const float*)d_in[6];
    const float* Wc = (const float*)d_in[7];
    const float* bc = (const float*)d_in[8];
    const float* Wo = (const float*)d_in[9];
    const float* bo = (const float*)d_in[10];
    float* out = (float*)d_out;

    static cudaStream_t s2 = nullptr;
    static cudaEvent_t evFork = nullptr, evJoin = nullptr;
    static bool inited = false;
    if (!inited) {
        cudaStreamCreateWithFlags(&s2, cudaStreamNonBlocking);
        cudaEventCreateWithFlags(&evFork, cudaEventDisableTiming);
        cudaEventCreateWithFlags(&evJoin, cudaEventDisableTiming);
        cudaFuncSetAttribute(gemm_lstm_kernel,
                             cudaFuncAttributeMaxDynamicSharedMemorySize, SMEM_TOTAL);
        inited = true;
    }

    // fork: pack_z on main stream, transpose_w on s2 (independent)
    cudaEventRecord(evFork, 0);
    cudaStreamWaitEvent(s2, evFork, 0);

    pack_z_kernel<<<(BROWS * KTOT / 8) / 256, 256>>>(x, h);

    dim3 tg(KTOT / 64, UNITS / 64, 4);
    transpose_w_kernel<<<tg, dim3(16, 16), 0, s2>>>(Wf, Wi, Wc, Wo);

    // join back to main stream
    cudaEventRecord(evJoin, s2);
    cudaStreamWaitEvent(0, evJoin, 0);

    int grid = (BROWS / BM) * (NTOT / BN);   // 2048
    gemm_lstm_kernel<<<grid, 256, SMEM_TOTAL>>>(c, bf, bi, bc, bo, out);
}